// round 15
// baseline (speedup 1.0000x reference)
#include <cuda_runtime.h>
#include <cuda_fp16.h>

#define D_IN   1024
#define D_FEAT 4096
#define DEG    4
#define RPB    8

// Shuffle-free FWHT + fp16 LDS.128 gather.
// Phase 1 (per warp; d = wid>>2, rows r = (wid&3)*2 + rr):
//   thread holds 32 CONSECUTIVE elements j = lane*32 + m  (low 5 bits in regs)
//   -> 5 register stages -> fp16 half2 transpose through stride-17 scratch
//   (STS.32 banks (17*lane+m)%32 all distinct; LDS.32 banks (k+lane/2)%32
//    distinct + pair-broadcast: both conflict-free) -> thread holds
//   i = k*32 + lane -> 5 register stages -> swizzled table store (as R5).
// Table, per degree d: 1024 idx x 16B; word w of idx = row-pair p = w ^ s(idx),
// s = (idx>>3)&3, even row low half. Phase-2: one LDS.128 per (feature,degree),
// fp32 products, coalesced STG.32 (R5's measured-best epilogue, bit-identical).
// rad (+-1) as sign bitmask; perm repacked to ushort4 per launch.

__device__ ushort4 g_perm16[D_FEAT];

__global__ void pack_perm_kernel(const int* __restrict__ perm) {
    int f = blockIdx.x * 256 + threadIdx.x;
    if (f < D_FEAT) {
        g_perm16[f] = make_ushort4((unsigned short)perm[f],
                                   (unsigned short)perm[D_FEAT + f],
                                   (unsigned short)perm[2 * D_FEAT + f],
                                   (unsigned short)perm[3 * D_FEAT + f]);
    }
}

// smem map (bytes): [0,65536) table ; [65536,66048) radw ; [66048,100864) scratch
#define SMEM_TOTAL 100864

__global__ __launch_bounds__(512, 2)
void srht_kernel(const float* __restrict__ x,
                 const float* __restrict__ rad,
                 const float* __restrict__ log_ls,
                 const float* __restrict__ log_var,
                 float* __restrict__ out)
{
    extern __shared__ __align__(16) unsigned char smem_raw[];
    __half*       tab   = reinterpret_cast<__half*>(smem_raw);         // [DEG][1024][8] swizzled
    const uint4*  tab4  = reinterpret_cast<const uint4*>(smem_raw);    // [DEG][1024]
    unsigned*     radw  = reinterpret_cast<unsigned*>(smem_raw + 65536);

    const int tid  = threadIdx.x;
    const int wid  = tid >> 5;          // 0..15
    const int lane = tid & 31;
    const int row0 = blockIdx.x * RPB;

    unsigned* __restrict__ scr =
        reinterpret_cast<unsigned*>(smem_raw + 66048) + wid * 544;  // stride-17, 544 words/warp

    // ---------------- Phase 0: build rad sign words (warps 0..3) ----------------
    if (wid < 4) {
        const float* __restrict__ rd = rad + wid * D_IN;
        #pragma unroll
        for (int k = 0; k < 32; k++) {
            float f = rd[k * 32 + lane];
            unsigned m = __ballot_sync(0xffffffffu, f < 0.0f);
            if (lane == (k & 31)) radw[wid * 32 + k] = m;
        }
    }
    __syncthreads();

    // ---------------- Phase 1: shuffle-free FWHT ----------------
    {
        const int d = wid >> 2;                 // 0..3
        const unsigned sw = radw[d * 32 + lane];   // sign bits for elements lane*32 + m

        #pragma unroll
        for (int rr = 0; rr < 2; rr++) {
            const int r = (wid & 3) * 2 + rr;   // 0..7
            const float4* __restrict__ xr4 =
                reinterpret_cast<const float4*>(x + (size_t)(row0 + r) * D_IN) + lane * 8;

            float v[32];                        // element j = lane*32 + m
            #pragma unroll
            for (int c = 0; c < 8; c++) {
                float4 q = xr4[c];
                const int m0 = 4 * c;
                v[m0+0] = __uint_as_float(__float_as_uint(q.x) ^ ((sw << (31 - (m0+0))) & 0x80000000u));
                v[m0+1] = __uint_as_float(__float_as_uint(q.y) ^ ((sw << (31 - (m0+1))) & 0x80000000u));
                v[m0+2] = __uint_as_float(__float_as_uint(q.z) ^ ((sw << (31 - (m0+2))) & 0x80000000u));
                v[m0+3] = __uint_as_float(__float_as_uint(q.w) ^ ((sw << (31 - (m0+3))) & 0x80000000u));
            }

            // stages h = 1..16 (low bits, in registers)
            #pragma unroll
            for (int mb = 0; mb < 5; mb++) {
                const int m = 1 << mb;
                #pragma unroll
                for (int k = 0; k < 32; k++) {
                    if ((k & m) == 0) {
                        float a = v[k], b = v[k + m];
                        v[k] = a + b;  v[k + m] = a - b;
                    }
                }
            }

            // 32x32 transpose via fp16 half2 scratch, stride 17 (conflict-free)
            #pragma unroll
            for (int mp = 0; mp < 16; mp++) {
                __half2 hp = __floats2half2_rn(v[2*mp], v[2*mp+1]);
                scr[lane * 17 + mp] = *reinterpret_cast<unsigned*>(&hp);
            }
            __syncwarp();
            {
                const int wsel = lane >> 1;
                const bool hi  = (lane & 1) != 0;
                #pragma unroll
                for (int k = 0; k < 32; k++) {
                    unsigned wd = scr[k * 17 + wsel];
                    float2 f2 = __half22float2(*reinterpret_cast<__half2*>(&wd));
                    v[k] = hi ? f2.y : f2.x;
                }
            }
            __syncwarp();    // scratch reusable for next rr

            // stages h = 32..512 (now in registers; thread holds i = k*32 + lane)
            #pragma unroll
            for (int mb = 0; mb < 5; mb++) {
                const int m = 1 << mb;
                #pragma unroll
                for (int k = 0; k < 32; k++) {
                    if ((k & m) == 0) {
                        float a = v[k], b = v[k + m];
                        v[k] = a + b;  v[k + m] = a - b;
                    }
                }
            }

            // conflict-free 16-bit swizzled table stores (as R5)
            const int ph = r >> 1, rh = r & 1;
            #pragma unroll
            for (int k = 0; k < 32; k++) {
                const int i = k * 32 + lane;
                const int w = ph ^ ((i >> 3) & 3);
                tab[d * 8192 + i * 8 + w * 2 + rh] = __float2half_rn(v[k]);
            }
        }
    }
    __syncthreads();

    // ---------------- Phase 2: gather (LDS.128/lane) + fp32 product + stores ----------------
    // oscale folds exp(log_var/2), 1/sqrt(D_FEAT), inv_lengthscale^DEG
    const float oscale = expf(0.5f * log_var[0] - 4.0f * log_ls[0]) * (1.0f / 64.0f);
    float* __restrict__ ob = out + (size_t)row0 * D_FEAT;

    #pragma unroll
    for (int it = 0; it < 8; it++) {
        const int f = it * 512 + wid * 32 + lane;   // this lane's feature

        const ushort4 pp = g_perm16[f];             // one LDG.64: all 4 degree-indices
        const int idxs[4] = { pp.x, pp.y, pp.z, pp.w };

        float a0 = oscale, a1 = oscale, a2 = oscale, a3 = oscale;
        float a4 = oscale, a5 = oscale, a6 = oscale, a7 = oscale;

        #pragma unroll
        for (int dd = 0; dd < DEG; dd++) {
            const int idx = idxs[dd];
            uint4 h = tab4[dd * 1024 + idx];        // whole idx: 8 rows fp16
            const int s = (idx >> 3) & 3;
            // branch-free un-swizzle: g[w] = h[w ^ s]
            unsigned hx = (s & 1) ? h.y : h.x;
            unsigned hy = (s & 1) ? h.x : h.y;
            unsigned hz = (s & 1) ? h.w : h.z;
            unsigned hw = (s & 1) ? h.z : h.w;
            unsigned g0 = (s & 2) ? hz : hx;
            unsigned g1 = (s & 2) ? hw : hy;
            unsigned g2 = (s & 2) ? hx : hz;
            unsigned g3 = (s & 2) ? hy : hw;

            float2 f0 = __half22float2(*reinterpret_cast<__half2*>(&g0));
            float2 f1 = __half22float2(*reinterpret_cast<__half2*>(&g1));
            float2 f2 = __half22float2(*reinterpret_cast<__half2*>(&g2));
            float2 f3 = __half22float2(*reinterpret_cast<__half2*>(&g3));
            a0 *= f0.x;  a1 *= f0.y;
            a2 *= f1.x;  a3 *= f1.y;
            a4 *= f2.x;  a5 *= f2.y;
            a6 *= f3.x;  a7 *= f3.y;
        }

        // 8 fully-coalesced 128B row stores
        ob[0 * D_FEAT + f] = a0;
        ob[1 * D_FEAT + f] = a1;
        ob[2 * D_FEAT + f] = a2;
        ob[3 * D_FEAT + f] = a3;
        ob[4 * D_FEAT + f] = a4;
        ob[5 * D_FEAT + f] = a5;
        ob[6 * D_FEAT + f] = a6;
        ob[7 * D_FEAT + f] = a7;
    }
}

extern "C" void kernel_launch(void* const* d_in, const int* in_sizes, int n_in,
                              void* d_out, int out_size)
{
    const float* x   = (const float*)d_in[0];
    const float* rad = (const float*)d_in[1];
    const int*   pm  = (const int*)d_in[2];
    const float* lls = (const float*)d_in[3];
    const float* lv  = (const float*)d_in[4];
    float* out = (float*)d_out;

    const int rows = in_sizes[0] / D_IN;            // 16384

    pack_perm_kernel<<<D_FEAT / 256, 256>>>(pm);

    cudaFuncSetAttribute(srht_kernel,
                         cudaFuncAttributeMaxDynamicSharedMemorySize, SMEM_TOTAL);
    srht_kernel<<<rows / RPB, 512, SMEM_TOTAL>>>(x, rad, lls, lv, out);
}

// round 16
// speedup vs baseline: 1.0831x; 1.0831x over previous
#include <cuda_runtime.h>
#include <cuda_fp16.h>

#define D_IN   1024
#define D_FEAT 4096
#define DEG    4
#define RPB    8

// fp16 table, per degree d: 1024 idx x 16B; word w of idx holds row-pair
// p = w ^ s(idx), s = (idx>>3)&3, even row in low half. Phase-1 STS.U16 is
// conflict-free (bank = 4*(lane&7) + ((r>>1) ^ ((lane>>3)&3))); phase-2 gather
// is one LDS.128 per (feature, degree). rad (+-1) compressed to sign words.
// Single kernel: perm read directly (4 coalesced LDG.32, L1-resident) --
// no pre-pack kernel in the graph (it cost 1.2-2.2us per replay).

__global__ __launch_bounds__(512, 2)
void srht_kernel(const float* __restrict__ x,
                 const float* __restrict__ rad,
                 const int*   __restrict__ perm,
                 const float* __restrict__ log_ls,
                 const float* __restrict__ log_var,
                 float* __restrict__ out)
{
    extern __shared__ __align__(16) unsigned char smem_raw[];
    __half*       tab   = reinterpret_cast<__half*>(smem_raw);         // [DEG][1024][8] swizzled
    const uint4*  tab4  = reinterpret_cast<const uint4*>(smem_raw);    // [DEG][1024]
    unsigned*     radw  = reinterpret_cast<unsigned*>(smem_raw + DEG * D_IN * RPB * 2);
    const uint4*  radw4 = reinterpret_cast<const uint4*>(radw);        // [DEG][8]

    const int tid  = threadIdx.x;
    const int wid  = tid >> 5;          // 0..15
    const int lane = tid & 31;
    const int row0 = blockIdx.x * RPB;

    // ---------------- Phase 0: build rad sign words (warps 0..3) ----------------
    if (wid < 4) {
        const float* __restrict__ rd = rad + wid * D_IN;
        #pragma unroll
        for (int k = 0; k < 32; k++) {
            float f = rd[k * 32 + lane];
            unsigned m = __ballot_sync(0xffffffffu, f < 0.0f);
            if (lane == (k & 31)) radw[wid * 32 + k] = m;
        }
    }
    __syncthreads();

    // ---------------- Phase 1: FWHT (shuffle scheme), sign via XOR ----------------
    {
        const int d = wid >> 2;                 // 0..3
        const int sh = 31 - lane;               // puts sign bit 'lane' at bit 31
        #pragma unroll
        for (int rr = 0; rr < 2; rr++) {
            const int r = (wid & 3) * 2 + rr;   // 0..7
            const float* __restrict__ xr = x + (size_t)(row0 + r) * D_IN;

            float v[32];                        // lane holds i = k*32 + lane
            #pragma unroll
            for (int kc = 0; kc < 8; kc++) {
                uint4 wq = radw4[d * 8 + kc];   // broadcast LDS.128: signs for k = 4kc..4kc+3
                #pragma unroll
                for (int j = 0; j < 4; j++) {
                    const int k = kc * 4 + j;
                    unsigned w = (j == 0) ? wq.x : (j == 1) ? wq.y : (j == 2) ? wq.z : wq.w;
                    unsigned xb = __float_as_uint(xr[k * 32 + lane]);
                    v[k] = __uint_as_float(xb ^ ((w << sh) & 0x80000000u));
                }
            }

            // lane-bit stages h = 1..16 via shuffle (free pipe on sm_103a)
            #pragma unroll
            for (int hb = 0; hb < 5; hb++) {
                const int h = 1 << hb;
                const bool up = (lane & h) != 0;
                #pragma unroll
                for (int k = 0; k < 32; k++) {
                    float o = __shfl_xor_sync(0xffffffffu, v[k], h);
                    v[k] = up ? (o - v[k]) : (v[k] + o);
                }
            }
            // register-bit stages h = 32..512
            #pragma unroll
            for (int mb = 0; mb < 5; mb++) {
                const int m = 1 << mb;
                #pragma unroll
                for (int k = 0; k < 32; k++) {
                    if ((k & m) == 0) {
                        float a = v[k], b = v[k + m];
                        v[k] = a + b;  v[k + m] = a - b;
                    }
                }
            }

            // conflict-free 16-bit swizzled stores
            const int ph = r >> 1, rh = r & 1;
            #pragma unroll
            for (int k = 0; k < 32; k++) {
                const int i = k * 32 + lane;
                const int w = ph ^ ((i >> 3) & 3);
                tab[d * 8192 + i * 8 + w * 2 + rh] = __float2half_rn(v[k]);
            }
        }
    }
    __syncthreads();

    // ---------------- Phase 2: gather (LDS.128/lane) + product + coalesced stores ----------------
    // oscale folds exp(log_var/2), 1/sqrt(D_FEAT), and inv_lengthscale^DEG
    const float oscale = expf(0.5f * log_var[0] - 4.0f * log_ls[0]) * (1.0f / 64.0f);
    float* __restrict__ ob = out + (size_t)row0 * D_FEAT;

    #pragma unroll
    for (int it = 0; it < 8; it++) {
        const int f = it * 512 + wid * 32 + lane;   // this lane's feature

        // hoisted coalesced perm loads (L1-resident after first block)
        const int i0 = perm[0 * D_FEAT + f];
        const int i1 = perm[1 * D_FEAT + f];
        const int i2 = perm[2 * D_FEAT + f];
        const int i3 = perm[3 * D_FEAT + f];
        const int idxs[4] = { i0, i1, i2, i3 };

        float a0 = oscale, a1 = oscale, a2 = oscale, a3 = oscale;
        float a4 = oscale, a5 = oscale, a6 = oscale, a7 = oscale;

        #pragma unroll
        for (int dd = 0; dd < DEG; dd++) {
            const int idx = idxs[dd];
            uint4 h = tab4[dd * 1024 + idx];        // whole idx: 8 rows fp16
            const int s = (idx >> 3) & 3;
            // branch-free un-swizzle: g[w] = h[w ^ s]
            unsigned hx = (s & 1) ? h.y : h.x;
            unsigned hy = (s & 1) ? h.x : h.y;
            unsigned hz = (s & 1) ? h.w : h.z;
            unsigned hw = (s & 1) ? h.z : h.w;
            unsigned g0 = (s & 2) ? hz : hx;
            unsigned g1 = (s & 2) ? hw : hy;
            unsigned g2 = (s & 2) ? hx : hz;
            unsigned g3 = (s & 2) ? hy : hw;

            float2 f0 = __half22float2(*reinterpret_cast<__half2*>(&g0));
            float2 f1 = __half22float2(*reinterpret_cast<__half2*>(&g1));
            float2 f2 = __half22float2(*reinterpret_cast<__half2*>(&g2));
            float2 f3 = __half22float2(*reinterpret_cast<__half2*>(&g3));
            a0 *= f0.x;  a1 *= f0.y;
            a2 *= f1.x;  a3 *= f1.y;
            a4 *= f2.x;  a5 *= f2.y;
            a6 *= f3.x;  a7 *= f3.y;
        }

        // 8 fully-coalesced 128B row stores
        ob[0 * D_FEAT + f] = a0;
        ob[1 * D_FEAT + f] = a1;
        ob[2 * D_FEAT + f] = a2;
        ob[3 * D_FEAT + f] = a3;
        ob[4 * D_FEAT + f] = a4;
        ob[5 * D_FEAT + f] = a5;
        ob[6 * D_FEAT + f] = a6;
        ob[7 * D_FEAT + f] = a7;
    }
}

extern "C" void kernel_launch(void* const* d_in, const int* in_sizes, int n_in,
                              void* d_out, int out_size)
{
    const float* x   = (const float*)d_in[0];
    const float* rad = (const float*)d_in[1];
    const int*   pm  = (const int*)d_in[2];
    const float* lls = (const float*)d_in[3];
    const float* lv  = (const float*)d_in[4];
    float* out = (float*)d_out;

    const int rows = in_sizes[0] / D_IN;                            // 16384
    const int smem = DEG * D_IN * RPB * (int)sizeof(__half) + 512;  // 66048 B

    cudaFuncSetAttribute(srht_kernel,
                         cudaFuncAttributeMaxDynamicSharedMemorySize, smem);
    srht_kernel<<<rows / RPB, 512, smem>>>(x, rad, pm, lls, lv, out);
}

// round 17
// speedup vs baseline: 1.1294x; 1.0427x over previous
#include <cuda_runtime.h>
#include <cuda_fp16.h>

#define D_IN   1024
#define D_FEAT 4096
#define DEG    4
#define RPB    8

// BEST-MEASURED CONFIGURATION (R5, 135.7us) — re-banked after 12 experiments.
// fp16 table, per degree d: 1024 idx x 16B; word w of idx holds row-pair
// p = w ^ s(idx), s = (idx>>3)&3, even row in low half.
//  - phase-1 STS.U16 conflict-free: bank = 4*(lane&7) + ((r>>1) ^ ((lane>>3)&3)).
//  - phase-2 gather: one LDS.128 per (feature, degree) fetches all 8 rows;
//    fp32 products; 8 coalesced 128B row stores.
// rad (+-1) compressed to sign bitmask words (XOR-applied, FMUL-free);
// perm packed once per launch into ushort4 (1 LDG.64 per feature, all degrees).
// Established empirically: SHFL is MIO-wavefront-free on sm_103a (keep the
// shuffle FWHT); LDS/STS cost full wavefronts; gather conflict excess over the
// 4-phase floor is structural given coalesced output stores.

__device__ ushort4 g_perm16[D_FEAT];

__global__ void pack_perm_kernel(const int* __restrict__ perm) {
    int f = blockIdx.x * 256 + threadIdx.x;
    if (f < D_FEAT) {
        g_perm16[f] = make_ushort4((unsigned short)perm[f],
                                   (unsigned short)perm[D_FEAT + f],
                                   (unsigned short)perm[2 * D_FEAT + f],
                                   (unsigned short)perm[3 * D_FEAT + f]);
    }
}

__global__ __launch_bounds__(512, 2)
void srht_kernel(const float* __restrict__ x,
                 const float* __restrict__ rad,
                 const float* __restrict__ log_ls,
                 const float* __restrict__ log_var,
                 float* __restrict__ out)
{
    extern __shared__ __align__(16) unsigned char smem_raw[];
    __half*       tab   = reinterpret_cast<__half*>(smem_raw);         // [DEG][1024][8] swizzled
    const uint4*  tab4  = reinterpret_cast<const uint4*>(smem_raw);    // [DEG][1024]
    unsigned*     radw  = reinterpret_cast<unsigned*>(smem_raw + DEG * D_IN * RPB * 2);
    const uint4*  radw4 = reinterpret_cast<const uint4*>(radw);        // [DEG][8]

    const int tid  = threadIdx.x;
    const int wid  = tid >> 5;          // 0..15
    const int lane = tid & 31;
    const int row0 = blockIdx.x * RPB;

    // ---------------- Phase 0: build rad sign words (warps 0..3) ----------------
    if (wid < 4) {
        const float* __restrict__ rd = rad + wid * D_IN;
        #pragma unroll
        for (int k = 0; k < 32; k++) {
            float f = rd[k * 32 + lane];
            unsigned m = __ballot_sync(0xffffffffu, f < 0.0f);
            if (lane == (k & 31)) radw[wid * 32 + k] = m;
        }
    }
    __syncthreads();

    // ---------------- Phase 1: FWHT (shuffle scheme), sign via XOR ----------------
    {
        const int d = wid >> 2;                 // 0..3
        const int sh = 31 - lane;               // puts sign bit 'lane' at bit 31
        #pragma unroll
        for (int rr = 0; rr < 2; rr++) {
            const int r = (wid & 3) * 2 + rr;   // 0..7
            const float* __restrict__ xr = x + (size_t)(row0 + r) * D_IN;

            float v[32];                        // lane holds i = k*32 + lane
            #pragma unroll
            for (int kc = 0; kc < 8; kc++) {
                uint4 wq = radw4[d * 8 + kc];   // broadcast LDS.128: signs for k = 4kc..4kc+3
                #pragma unroll
                for (int j = 0; j < 4; j++) {
                    const int k = kc * 4 + j;
                    unsigned w = (j == 0) ? wq.x : (j == 1) ? wq.y : (j == 2) ? wq.z : wq.w;
                    unsigned xb = __float_as_uint(xr[k * 32 + lane]);
                    v[k] = __uint_as_float(xb ^ ((w << sh) & 0x80000000u));
                }
            }

            // lane-bit stages h = 1..16 via shuffle (wavefront-free pipe)
            #pragma unroll
            for (int hb = 0; hb < 5; hb++) {
                const int h = 1 << hb;
                const bool up = (lane & h) != 0;
                #pragma unroll
                for (int k = 0; k < 32; k++) {
                    float o = __shfl_xor_sync(0xffffffffu, v[k], h);
                    v[k] = up ? (o - v[k]) : (v[k] + o);
                }
            }
            // register-bit stages h = 32..512
            #pragma unroll
            for (int mb = 0; mb < 5; mb++) {
                const int m = 1 << mb;
                #pragma unroll
                for (int k = 0; k < 32; k++) {
                    if ((k & m) == 0) {
                        float a = v[k], b = v[k + m];
                        v[k] = a + b;  v[k + m] = a - b;
                    }
                }
            }

            // conflict-free 16-bit swizzled stores
            const int ph = r >> 1, rh = r & 1;
            #pragma unroll
            for (int k = 0; k < 32; k++) {
                const int i = k * 32 + lane;
                const int w = ph ^ ((i >> 3) & 3);
                tab[d * 8192 + i * 8 + w * 2 + rh] = __float2half_rn(v[k]);
            }
        }
    }
    __syncthreads();

    // ---------------- Phase 2: gather (LDS.128/lane) + product + coalesced stores ----------------
    // oscale folds exp(log_var/2), 1/sqrt(D_FEAT), and inv_lengthscale^DEG
    const float oscale = expf(0.5f * log_var[0] - 4.0f * log_ls[0]) * (1.0f / 64.0f);
    float* __restrict__ ob = out + (size_t)row0 * D_FEAT;

    #pragma unroll
    for (int it = 0; it < 8; it++) {
        const int f = it * 512 + wid * 32 + lane;   // this lane's feature

        const ushort4 pp = g_perm16[f];             // one LDG.64: all 4 degree-indices
        const int idx0 = pp.x, idx1 = pp.y, idx2 = pp.z, idx3 = pp.w;

        float a0 = oscale, a1 = oscale, a2 = oscale, a3 = oscale;
        float a4 = oscale, a5 = oscale, a6 = oscale, a7 = oscale;

        #pragma unroll
        for (int dd = 0; dd < DEG; dd++) {
            const int idx = (dd == 0) ? idx0 : (dd == 1) ? idx1 : (dd == 2) ? idx2 : idx3;
            uint4 h = tab4[dd * 1024 + idx];        // whole idx: 8 rows fp16
            const int s = (idx >> 3) & 3;
            // branch-free un-swizzle: g[w] = h[w ^ s]
            unsigned hx = (s & 1) ? h.y : h.x;
            unsigned hy = (s & 1) ? h.x : h.y;
            unsigned hz = (s & 1) ? h.w : h.z;
            unsigned hw = (s & 1) ? h.z : h.w;
            unsigned g0 = (s & 2) ? hz : hx;
            unsigned g1 = (s & 2) ? hw : hy;
            unsigned g2 = (s & 2) ? hx : hz;
            unsigned g3 = (s & 2) ? hy : hw;

            float2 f0 = __half22float2(*reinterpret_cast<__half2*>(&g0));
            float2 f1 = __half22float2(*reinterpret_cast<__half2*>(&g1));
            float2 f2 = __half22float2(*reinterpret_cast<__half2*>(&g2));
            float2 f3 = __half22float2(*reinterpret_cast<__half2*>(&g3));
            a0 *= f0.x;  a1 *= f0.y;
            a2 *= f1.x;  a3 *= f1.y;
            a4 *= f2.x;  a5 *= f2.y;
            a6 *= f3.x;  a7 *= f3.y;
        }

        // 8 fully-coalesced 128B row stores
        ob[0 * D_FEAT + f] = a0;
        ob[1 * D_FEAT + f] = a1;
        ob[2 * D_FEAT + f] = a2;
        ob[3 * D_FEAT + f] = a3;
        ob[4 * D_FEAT + f] = a4;
        ob[5 * D_FEAT + f] = a5;
        ob[6 * D_FEAT + f] = a6;
        ob[7 * D_FEAT + f] = a7;
    }
}

extern "C" void kernel_launch(void* const* d_in, const int* in_sizes, int n_in,
                              void* d_out, int out_size)
{
    const float* x   = (const float*)d_in[0];
    const float* rad = (const float*)d_in[1];
    const int*   pm  = (const int*)d_in[2];
    const float* lls = (const float*)d_in[3];
    const float* lv  = (const float*)d_in[4];
    float* out = (float*)d_out;

    const int rows = in_sizes[0] / D_IN;                            // 16384
    const int smem = DEG * D_IN * RPB * (int)sizeof(__half) + 512;  // 66048 B

    pack_perm_kernel<<<D_FEAT / 256, 256>>>(pm);

    cudaFuncSetAttribute(srht_kernel,
                         cudaFuncAttributeMaxDynamicSharedMemorySize, smem);
    srht_kernel<<<rows / RPB, 512, smem>>>(x, rad, lls, lv, out);
}